// round 13
// baseline (speedup 1.0000x reference)
#include <cuda_runtime.h>
#include <math_constants.h>

#define ROWLEN 8192
#define NROWS  4096
#define K      8
#define SLICES 8                          // slices per row
#define SLICE  (ROWLEN / SLICES)          // 1024 elements per warp-task
#define NF4    (SLICE / 4 / 32)           // 8 float4 per lane
#define TPB_A  256
#define GRID_A 608                        // 152 SMs x 4 CTAs, persistent
#define NTASK  (NROWS * SLICES)
#define FULL   0xffffffffu

// Intermediate: per (row, slice) a sorted-desc top-8 key list. 2 MB.
__device__ unsigned long long g_slice[(size_t)NTASK * K];

// Order-preserving map: float -> uint32 (f1 > f2 <=> u1 > u2).
__device__ __forceinline__ unsigned fflip(float f) {
    unsigned u = __float_as_uint(f);
    return (u & 0x80000000u) ? ~u : (u | 0x80000000u);
}
__device__ __forceinline__ float funflip(unsigned u) {
    return __uint_as_float((u & 0x80000000u) ? (u ^ 0x80000000u) : ~u);
}
__device__ __forceinline__ unsigned long long mkkey(float f, int idx) {
    // tie-break: smaller index wins -> complement index in low bits
    return ((unsigned long long)fflip(f) << 32) | (unsigned)(ROWLEN - 1 - idx);
}

// Guarded insert into sorted-descending register top-8.
__device__ __forceinline__ void insert8(unsigned long long (&t)[K],
                                        unsigned long long key) {
    if (key > t[K - 1]) {
        t[K - 1] = key;
#pragma unroll
        for (int s = K - 1; s > 0; s--) {
            unsigned long long a = t[s - 1], b = t[s];
            t[s - 1] = a > b ? a : b;
            t[s]     = a > b ? b : a;
        }
    }
}

// Bitonic top-8 merge of two sorted-desc 8-lists in smem: dst <- top8(dst,src).
__device__ __forceinline__ void merge8(unsigned long long* dst,
                                       const unsigned long long* src) {
    unsigned long long m[K];
#pragma unroll
    for (int j = 0; j < K; j++) {
        unsigned long long a = dst[j], b = src[K - 1 - j];
        m[j] = a > b ? a : b;
    }
#pragma unroll
    for (int d = K / 2; d >= 1; d >>= 1) {
#pragma unroll
        for (int j = 0; j < K; j++) {
            if ((j & d) == 0) {
                unsigned long long lo = m[j], hi = m[j | d];
                m[j]     = lo > hi ? lo : hi;
                m[j | d] = lo > hi ? hi : lo;
            }
        }
    }
#pragma unroll
    for (int j = 0; j < K; j++) dst[j] = m[j];
}

// ---------------- Kernel A: per-slice top-8, warp-autonomous ----------------
__global__ __launch_bounds__(TPB_A, 4)
void slice_topk_kernel(const float* __restrict__ x) {
    const int lane = threadIdx.x & 31;
    const int gwarp = (blockIdx.x * TPB_A + threadIdx.x) >> 5;
    const int nwarps = GRID_A * (TPB_A / 32);

    for (int task = gwarp; task < NTASK; task += nwarps) {
        const int row   = task >> 3;
        const int slice = task & (SLICES - 1);
        const float4* __restrict__ p = reinterpret_cast<const float4*>(
            x + (size_t)row * ROWLEN + slice * SLICE);

        // -- burst-load 32 elements per lane (8 consecutive LDG.128) --
        float4 v[NF4];
#pragma unroll
        for (int i = 0; i < NF4; i++) v[i] = p[lane + i * 32];

        float tmax = -CUDART_INF_F;
#pragma unroll
        for (int i = 0; i < NF4; i++)
            tmax = fmaxf(tmax, fmaxf(fmaxf(v[i].x, v[i].y), fmaxf(v[i].z, v[i].w)));

        // -- warp bitonic (ascending) of 32 thread-maxes; 8th largest @ lane 24 --
        float s = tmax;
#pragma unroll
        for (int k = 2; k <= 32; k <<= 1) {
#pragma unroll
            for (int j = k >> 1; j > 0; j >>= 1) {
                float o = __shfl_xor_sync(FULL, s, j);
                bool dir_asc = ((lane & k) == 0);
                bool lower   = ((lane & j) == 0);
                s = (dir_asc != lower) ? fmaxf(s, o) : fminf(s, o);
            }
        }
        const float t8 = __shfl_sync(FULL, s, 24);
        // >=8 slice elements are >= t8, and slice top-8 all >= t8 (subset prop).

        // -- exact survivor loop: all lanes build identical top-8 --
        unsigned long long top[K];
#pragma unroll
        for (int j = 0; j < K; j++) top[j] = 0ULL;

#pragma unroll
        for (int i = 0; i < NF4; i++) {
            float mi = fmaxf(fmaxf(v[i].x, v[i].y), fmaxf(v[i].z, v[i].w));
            unsigned mask = __ballot_sync(FULL, mi >= t8);
            while (mask) {                       // uniform across the warp
                int src = __ffs(mask) - 1;
                mask &= mask - 1;
                float a = __shfl_sync(FULL, v[i].x, src);
                float b = __shfl_sync(FULL, v[i].y, src);
                float c = __shfl_sync(FULL, v[i].z, src);
                float d = __shfl_sync(FULL, v[i].w, src);
                const int col = slice * SLICE + (src + i * 32) * 4;
                if (a >= t8) insert8(top, mkkey(a, col + 0));
                if (b >= t8) insert8(top, mkkey(b, col + 1));
                if (c >= t8) insert8(top, mkkey(c, col + 2));
                if (d >= t8) insert8(top, mkkey(d, col + 3));
            }
        }

        // -- lane j < 8 writes top[j] (register-select, then one STG.64) --
        unsigned long long myk = top[0];
#pragma unroll
        for (int j = 1; j < K; j++)
            if (lane == j) myk = top[j];
        if (lane < K) g_slice[(size_t)task * K + lane] = myk;
    }
}

// ---------------- Kernel B: merge 8 slice lists per row ----------------
#define TPB_B 256
__global__ __launch_bounds__(TPB_B)
void merge_rows_kernel(float* __restrict__ out_vals,
                       float* __restrict__ out_idx) {
    __shared__ unsigned long long buf[TPB_B / 32][SLICES * K];  // 8 x 64 keys
    const int warp = threadIdx.x >> 5;
    const int lane = threadIdx.x & 31;
    const int row  = blockIdx.x * (TPB_B / 32) + warp;

    const unsigned long long* __restrict__ src = &g_slice[(size_t)row * SLICES * K];
    buf[warp][lane]      = src[lane];
    buf[warp][lane + 32] = src[lane + 32];
    __syncwarp();

    if (lane < 4) merge8(&buf[warp][lane * 16], &buf[warp][lane * 16 + 8]);
    __syncwarp();
    if (lane < 2) merge8(&buf[warp][lane * 32], &buf[warp][lane * 32 + 16]);
    __syncwarp();
    if (lane == 0) merge8(&buf[warp][0], &buf[warp][32]);
    __syncwarp();

    if (lane < K) {
        unsigned long long key = buf[warp][lane];
        out_vals[(size_t)row * K + lane] = funflip((unsigned)(key >> 32));
        out_idx [(size_t)row * K + lane] =
            (float)(ROWLEN - 1 - (unsigned)(key & 0xFFFFFFFFu));
    }
}

extern "C" void kernel_launch(void* const* d_in, const int* in_sizes, int n_in,
                              void* d_out, int out_size) {
    const float* x = (const float*)d_in[0];
    float* out_vals = (float*)d_out;
    float* out_idx  = out_vals + (size_t)NROWS * K;
    slice_topk_kernel<<<GRID_A, TPB_A>>>(x);
    merge_rows_kernel<<<NROWS / (TPB_B / 32), TPB_B>>>(out_vals, out_idx);
}

// round 14
// speedup vs baseline: 1.0061x; 1.0061x over previous
#include <cuda_runtime.h>
#include <math_constants.h>

#define ROWLEN 8192
#define NROWS  4096
#define K      8
#define SLICES 8                          // slices per row
#define SLICE  (ROWLEN / SLICES)          // 1024 elements per warp-task
#define NF4    (SLICE / 4 / 32)           // 8 float4 per lane
#define TPB_A  256
#define GRID_A 608                        // 152 SMs x 4 CTAs, persistent
#define NTASK  (NROWS * SLICES)
#define FULL   0xffffffffu

// Intermediate: per (row, slice) a sorted-desc top-8 key list. 2 MB.
__device__ unsigned long long g_slice[(size_t)NTASK * K];

// Order-preserving map: float -> uint32 (f1 > f2 <=> u1 > u2).
__device__ __forceinline__ unsigned fflip(float f) {
    unsigned u = __float_as_uint(f);
    return (u & 0x80000000u) ? ~u : (u | 0x80000000u);
}
__device__ __forceinline__ float funflip(unsigned u) {
    return __uint_as_float((u & 0x80000000u) ? (u ^ 0x80000000u) : ~u);
}
__device__ __forceinline__ unsigned long long mkkey(float f, int idx) {
    // tie-break: smaller index wins -> complement index in low bits
    return ((unsigned long long)fflip(f) << 32) | (unsigned)(ROWLEN - 1 - idx);
}

// Guarded insert into sorted-descending register top-8.
__device__ __forceinline__ void insert8(unsigned long long (&t)[K],
                                        unsigned long long key) {
    if (key > t[K - 1]) {
        t[K - 1] = key;
#pragma unroll
        for (int s = K - 1; s > 0; s--) {
            unsigned long long a = t[s - 1], b = t[s];
            t[s - 1] = a > b ? a : b;
            t[s]     = a > b ? b : a;
        }
    }
}

// Bitonic top-8 merge of two sorted-desc 8-lists in smem: dst <- top8(dst,src).
__device__ __forceinline__ void merge8(unsigned long long* dst,
                                       const unsigned long long* src) {
    unsigned long long m[K];
#pragma unroll
    for (int j = 0; j < K; j++) {
        unsigned long long a = dst[j], b = src[K - 1 - j];
        m[j] = a > b ? a : b;
    }
#pragma unroll
    for (int d = K / 2; d >= 1; d >>= 1) {
#pragma unroll
        for (int j = 0; j < K; j++) {
            if ((j & d) == 0) {
                unsigned long long lo = m[j], hi = m[j | d];
                m[j]     = lo > hi ? lo : hi;
                m[j | d] = lo > hi ? hi : lo;
            }
        }
    }
#pragma unroll
    for (int j = 0; j < K; j++) dst[j] = m[j];
}

// ---------------- Kernel A: per-slice top-8, warp-autonomous ----------------
__global__ __launch_bounds__(TPB_A, 4)
void slice_topk_kernel(const float* __restrict__ x) {
    const int lane = threadIdx.x & 31;
    const int gwarp = (blockIdx.x * TPB_A + threadIdx.x) >> 5;
    const int nwarps = GRID_A * (TPB_A / 32);

    for (int task = gwarp; task < NTASK; task += nwarps) {
        const int row   = task >> 3;
        const int slice = task & (SLICES - 1);
        const float4* __restrict__ p = reinterpret_cast<const float4*>(
            x + (size_t)row * ROWLEN + slice * SLICE);

        // -- burst-load 32 elements per lane (8 consecutive LDG.128) --
        float4 v[NF4];
#pragma unroll
        for (int i = 0; i < NF4; i++) v[i] = p[lane + i * 32];

        float tmax = -CUDART_INF_F;
#pragma unroll
        for (int i = 0; i < NF4; i++)
            tmax = fmaxf(tmax, fmaxf(fmaxf(v[i].x, v[i].y), fmaxf(v[i].z, v[i].w)));

        // -- warp bitonic (ascending) of 32 thread-maxes; 8th largest @ lane 24 --
        float s = tmax;
#pragma unroll
        for (int k = 2; k <= 32; k <<= 1) {
#pragma unroll
            for (int j = k >> 1; j > 0; j >>= 1) {
                float o = __shfl_xor_sync(FULL, s, j);
                bool dir_asc = ((lane & k) == 0);
                bool lower   = ((lane & j) == 0);
                s = (dir_asc != lower) ? fmaxf(s, o) : fminf(s, o);
            }
        }
        const float t8 = __shfl_sync(FULL, s, 24);
        // >=8 slice elements are >= t8, and slice top-8 all >= t8 (subset prop).

        // -- exact survivor loop: all lanes build identical top-8 --
        unsigned long long top[K];
#pragma unroll
        for (int j = 0; j < K; j++) top[j] = 0ULL;

#pragma unroll
        for (int i = 0; i < NF4; i++) {
            float mi = fmaxf(fmaxf(v[i].x, v[i].y), fmaxf(v[i].z, v[i].w));
            unsigned mask = __ballot_sync(FULL, mi >= t8);
            while (mask) {                       // uniform across the warp
                int src = __ffs(mask) - 1;
                mask &= mask - 1;
                float a = __shfl_sync(FULL, v[i].x, src);
                float b = __shfl_sync(FULL, v[i].y, src);
                float c = __shfl_sync(FULL, v[i].z, src);
                float d = __shfl_sync(FULL, v[i].w, src);
                const int col = slice * SLICE + (src + i * 32) * 4;
                if (a >= t8) insert8(top, mkkey(a, col + 0));
                if (b >= t8) insert8(top, mkkey(b, col + 1));
                if (c >= t8) insert8(top, mkkey(c, col + 2));
                if (d >= t8) insert8(top, mkkey(d, col + 3));
            }
        }

        // -- lane j < 8 writes top[j] (register-select, then one STG.64) --
        unsigned long long myk = top[0];
#pragma unroll
        for (int j = 1; j < K; j++)
            if (lane == j) myk = top[j];
        if (lane < K) g_slice[(size_t)task * K + lane] = myk;
    }
}

// ---------------- Kernel B: merge 8 slice lists per row ----------------
#define TPB_B 256
__global__ __launch_bounds__(TPB_B)
void merge_rows_kernel(float* __restrict__ out_vals,
                       float* __restrict__ out_idx) {
    __shared__ unsigned long long buf[TPB_B / 32][SLICES * K];  // 8 x 64 keys
    const int warp = threadIdx.x >> 5;
    const int lane = threadIdx.x & 31;
    const int row  = blockIdx.x * (TPB_B / 32) + warp;

    const unsigned long long* __restrict__ src = &g_slice[(size_t)row * SLICES * K];
    buf[warp][lane]      = src[lane];
    buf[warp][lane + 32] = src[lane + 32];
    __syncwarp();

    if (lane < 4) merge8(&buf[warp][lane * 16], &buf[warp][lane * 16 + 8]);
    __syncwarp();
    if (lane < 2) merge8(&buf[warp][lane * 32], &buf[warp][lane * 32 + 16]);
    __syncwarp();
    if (lane == 0) merge8(&buf[warp][0], &buf[warp][32]);
    __syncwarp();

    if (lane < K) {
        unsigned long long key = buf[warp][lane];
        out_vals[(size_t)row * K + lane] = funflip((unsigned)(key >> 32));
        out_idx [(size_t)row * K + lane] =
            (float)(ROWLEN - 1 - (unsigned)(key & 0xFFFFFFFFu));
    }
}

extern "C" void kernel_launch(void* const* d_in, const int* in_sizes, int n_in,
                              void* d_out, int out_size) {
    const float* x = (const float*)d_in[0];
    float* out_vals = (float*)d_out;
    float* out_idx  = out_vals + (size_t)NROWS * K;
    slice_topk_kernel<<<GRID_A, TPB_A>>>(x);
    merge_rows_kernel<<<NROWS / (TPB_B / 32), TPB_B>>>(out_vals, out_idx);
}